// round 16
// baseline (speedup 1.0000x reference)
#include <cuda_runtime.h>
#include <cuda_fp16.h>
#include <math.h>
#include <stdint.h>

#define BATCH 2
#define SEQ   2048
#define DIM   1024
#define NH    16
#define HD    64
#define NTOK  (BATCH * SEQ)   // 4096

// ---------------- scratch (device globals) ---------------------------------
__device__ float  g_x1 [(size_t)NTOK * DIM];       // residual after proj
__device__ __half g_qkv[(size_t)NTOK * 3 * DIM];   // qkv fp16
__device__ __half g_h  [(size_t)NTOK * DIM];       // LN out fp16
__device__ __half g_y  [(size_t)NTOK * DIM];       // attn out fp16
__device__ __half g_act[(size_t)NTOK * 4 * DIM];   // relu(fc) fp16
__device__ __half g_wq [(size_t)3 * DIM * DIM];    // W_qkv^T fp16
__device__ __half g_wp [(size_t)DIM * DIM];        // W_proj^T fp16
__device__ __half g_wf [(size_t)4 * DIM * DIM];    // W_fc^T fp16
__device__ __half g_wo [(size_t)4 * DIM * DIM];    // W_out^T fp16

// ======================= helpers ===========================================
__device__ __forceinline__ uint32_t smem_u32(const void* p) {
    uint32_t a;
    asm("{ .reg .u64 t; cvta.to.shared.u64 t, %1; cvt.u32.u64 %0, t; }"
        : "=r"(a) : "l"(p));
    return a;
}
#define SWZ128(o) ((o) ^ (((o) >> 3) & 0x70))

__device__ __forceinline__ void ldsm_x4(uint32_t* r, uint32_t addr) {
    asm volatile("ldmatrix.sync.aligned.m8n8.x4.shared.b16 {%0,%1,%2,%3}, [%4];"
                 : "=r"(r[0]), "=r"(r[1]), "=r"(r[2]), "=r"(r[3]) : "r"(addr));
}
__device__ __forceinline__ void ldsm_x4t(uint32_t* r, uint32_t addr) {
    asm volatile("ldmatrix.sync.aligned.m8n8.x4.trans.shared.b16 {%0,%1,%2,%3}, [%4];"
                 : "=r"(r[0]), "=r"(r[1]), "=r"(r[2]), "=r"(r[3]) : "r"(addr));
}
__device__ __forceinline__ void mma_f16(float* c, const uint32_t* a,
                                        const uint32_t* b) {
    asm volatile(
        "mma.sync.aligned.m16n8k16.row.col.f32.f16.f16.f32 "
        "{%0,%1,%2,%3}, {%4,%5,%6,%7}, {%8,%9}, {%0,%1,%2,%3};"
        : "+f"(c[0]), "+f"(c[1]), "+f"(c[2]), "+f"(c[3])
        : "r"(a[0]), "r"(a[1]), "r"(a[2]), "r"(a[3]), "r"(b[0]), "r"(b[1]));
}
// fp16-accumulator variant (2-reg D) for the QK logits
__device__ __forceinline__ void mma_f16h(uint32_t* c, const uint32_t* a,
                                         const uint32_t* b) {
    asm volatile(
        "mma.sync.aligned.m16n8k16.row.col.f16.f16.f16.f16 "
        "{%0,%1}, {%2,%3,%4,%5}, {%6,%7}, {%0,%1};"
        : "+r"(c[0]), "+r"(c[1])
        : "r"(a[0]), "r"(a[1]), "r"(a[2]), "r"(a[3]), "r"(b[0]), "r"(b[1]));
}
__device__ __forceinline__ void cp16(uint32_t daddr, const void* saddr) {
    asm volatile("cp.async.cg.shared.global [%0], [%1], 16;"
                 :: "r"(daddr), "l"(saddr));
}
__device__ __forceinline__ float ex2(float x) {
    float y;
    asm("ex2.approx.f32 %0, %1;" : "=f"(y) : "f"(x));
    return y;
}
__device__ __forceinline__ uint32_t h2u(__half2 v) {
    return *reinterpret_cast<uint32_t*>(&v);
}
__device__ __forceinline__ __half2 u2h(uint32_t v) {
    return *reinterpret_cast<__half2*>(&v);
}

// ---------------- LayerNorm body (fp16 out) --------------------------------
__device__ __forceinline__ void ln_body(
    const float* __restrict__ x, const float* __restrict__ gamma,
    const float* __restrict__ beta, __half* __restrict__ out, int row)
{
    int tid = threadIdx.x;
    const float4* xr = reinterpret_cast<const float4*>(x + (size_t)row * DIM);
    float4 v = xr[tid];
    float s1 = v.x + v.y + v.z + v.w;
    float s2 = v.x * v.x + v.y * v.y + v.z * v.z + v.w * v.w;
    #pragma unroll
    for (int o = 16; o > 0; o >>= 1) {
        s1 += __shfl_xor_sync(0xffffffffu, s1, o);
        s2 += __shfl_xor_sync(0xffffffffu, s2, o);
    }
    __shared__ float sh1[8], sh2[8];
    int w = tid >> 5, l = tid & 31;
    if (l == 0) { sh1[w] = s1; sh2[w] = s2; }
    __syncthreads();
    s1 = 0.f; s2 = 0.f;
    #pragma unroll
    for (int i = 0; i < 8; i++) { s1 += sh1[i]; s2 += sh2[i]; }
    float mu  = s1 * (1.0f / DIM);
    float var = s2 * (1.0f / DIM) - mu * mu;
    float r   = rsqrtf(var + 1e-5f);
    float4 gv = reinterpret_cast<const float4*>(gamma)[tid];
    float4 bv = reinterpret_cast<const float4*>(beta)[tid];
    uint2 u;
    u.x = h2u(__floats2half2_rn((v.x - mu) * r * gv.x + bv.x,
                                (v.y - mu) * r * gv.y + bv.y));
    u.y = h2u(__floats2half2_rn((v.z - mu) * r * gv.z + bv.z,
                                (v.w - mu) * r * gv.w + bv.w));
    *reinterpret_cast<uint2*>(out + (size_t)row * DIM + tid * 4) = u;
}

__global__ __launch_bounds__(256) void ln_kernel(
    const float* __restrict__ x, const float* __restrict__ gamma,
    const float* __restrict__ beta, __half* __restrict__ out)
{
    ln_body(x, gamma, beta, out, blockIdx.x);
}

// ---------------- prep: 4 weight transposes + LN1, one launch --------------
__global__ __launch_bounds__(256) void prep_kernel(
    const float* __restrict__ W0, const float* __restrict__ W1,
    const float* __restrict__ W2, const float* __restrict__ W3,
    __half* __restrict__ O0, __half* __restrict__ O1,
    __half* __restrict__ O2, __half* __restrict__ O3,
    const float* __restrict__ x, const float* __restrict__ ln1_g,
    const float* __restrict__ ln1_b, __half* __restrict__ h)
{
    int t = blockIdx.x;
    if (t >= 12288) {
        ln_body(x, ln1_g, ln1_b, h, t - 12288);
        return;
    }
    const float* in; __half* out; int R, C;
    if (t < 3072)      { in = W0; out = O0; R = DIM;     C = 3 * DIM; }
    else if (t < 4096) { in = W1; out = O1; R = DIM;     C = DIM;     t -= 3072; }
    else if (t < 8192) { in = W2; out = O2; R = DIM;     C = 4 * DIM; t -= 4096; }
    else               { in = W3; out = O3; R = 4 * DIM; C = DIM;     t -= 8192; }
    int tilesX = C >> 5;
    int bx = t % tilesX, by = t / tilesX;

    __shared__ float tt[32][33];
    int tx = threadIdx.x & 31, ty = threadIdx.x >> 5;
    int x0 = bx * 32 + tx;
    #pragma unroll
    for (int j = 0; j < 32; j += 8)
        tt[ty + j][tx] = in[(size_t)(by * 32 + ty + j) * C + x0];
    __syncthreads();
    #pragma unroll
    for (int j = 0; j < 32; j += 8) {
        size_t idx = (size_t)(bx * 32 + ty + j) * R + by * 32 + tx;
        out[idx] = __float2half(tt[tx][ty + j]);
    }
}

// ---------------- fp16 GEMM (128x64 tile, 2-stage, 128 thr, 4 CTA/SM) ------
// A [M,K] fp16 row-major; B [N,K] fp16 row-major. fp32 accumulate.
// 4 warps (2m x 2n), warp tile 64x32. Stage = A 16KB + B 8KB = 24KB.
#define STAGE_BYTES 24576
#define GEMM_SMEM   (2 * STAGE_BYTES)

template<int MODE>   // 0: fp32+bias; 1: fp32+bias+res; 2: fp16 relu; 3: fp16
__global__ __launch_bounds__(128, 4) void gemm_f16(
    const __half* __restrict__ A, const __half* __restrict__ B,
    const float* __restrict__ bias, const float* __restrict__ res,
    float* __restrict__ C, __half* __restrict__ Oh, int M, int N, int K)
{
    extern __shared__ char smem[];
    const uint32_t sbase = smem_u32(smem);
    const int tid = threadIdx.x;
    const int wid = tid >> 5, lane = tid & 31;
    const int m0 = blockIdx.y * 128, n0 = blockIdx.x * 64;
    const int wm = (wid & 1) * 64;
    const int wn = (wid >> 1) * 32;

    float acc[4][4][4];
    #pragma unroll
    for (int a = 0; a < 4; a++)
        #pragma unroll
        for (int b = 0; b < 4; b++)
            #pragma unroll
            for (int c = 0; c < 4; c++) acc[a][b][c] = 0.f;

    const __half* Ab = A + (size_t)m0 * K;
    const __half* Bb = B + (size_t)n0 * K;

    // stage layout: A tile 16KB (128 rows x 128B), B tile 8KB (64 rows x 128B)
    auto issue = [&](int i) {
        int k0 = i << 6;
        uint32_t st = sbase + (uint32_t)(i & 1) * STAGE_BYTES;
        #pragma unroll
        for (int p = 0; p < 12; p++) {
            int idx = p * 128 + tid;              // 0..1535 (16B chunks)
            if (idx < 1024) {
                int row = idx >> 3, c = idx & 7;
                cp16(st + SWZ128((uint32_t)(row * 128 + c * 16)),
                     Ab + (size_t)row * K + k0 + c * 8);
            } else {
                int rem = idx - 1024;
                int row = rem >> 3, c = rem & 7;
                cp16(st + 16384 + SWZ128((uint32_t)(row * 128 + c * 16)),
                     Bb + (size_t)row * K + k0 + c * 8);
            }
        }
        asm volatile("cp.async.commit_group;" ::: "memory");
    };

    const int NC = K >> 6;
    issue(0);
    for (int i = 0; i < NC; i++) {
        asm volatile("cp.async.wait_group 0;" ::: "memory");
        __syncthreads();            // fill(i) visible; buffer i-1 fully consumed
        if (i + 1 < NC) issue(i + 1);   // other buffer, overlaps compute below

        uint32_t st = sbase + (uint32_t)(i & 1) * STAGE_BYTES;
        uint32_t sA = st, sB = st + 16384;

        #pragma unroll
        for (int ks = 0; ks < 4; ks++) {
            uint32_t af[4][4];
            #pragma unroll
            for (int mi = 0; mi < 4; mi++) {
                int row = wm + mi * 16 + (lane & 15);
                int colb = ks * 32 + (lane >> 4) * 16;
                ldsm_x4(af[mi], sA + SWZ128((uint32_t)(row * 128 + colb)));
            }
            uint32_t bf[2][4];
            #pragma unroll
            for (int ni2 = 0; ni2 < 2; ni2++) {
                int row = wn + ni2 * 16 + ((lane & 16) >> 1) + (lane & 7);
                int colb = ks * 32 + (lane & 8) * 2;
                ldsm_x4(bf[ni2], sB + SWZ128((uint32_t)(row * 128 + colb)));
            }
            #pragma unroll
            for (int mi = 0; mi < 4; mi++)
                #pragma unroll
                for (int ni2 = 0; ni2 < 2; ni2++) {
                    mma_f16(acc[mi][2 * ni2],     af[mi], bf[ni2]);
                    mma_f16(acc[mi][2 * ni2 + 1], af[mi], bf[ni2] + 2);
                }
        }
        __syncthreads();            // done with buffer i before its refill
    }

    #pragma unroll
    for (int mi = 0; mi < 4; mi++) {
        #pragma unroll
        for (int h = 0; h < 2; h++) {
            int row = m0 + wm + mi * 16 + (lane >> 2) + h * 8;
            #pragma unroll
            for (int ni = 0; ni < 4; ni++) {
                int col = n0 + wn + ni * 8 + (lane & 3) * 2;
                float2 bb = *reinterpret_cast<const float2*>(bias + col);
                float vx = acc[mi][ni][h * 2 + 0] + bb.x;
                float vy = acc[mi][ni][h * 2 + 1] + bb.y;
                if (MODE == 1) {
                    float2 rv = *reinterpret_cast<const float2*>(
                        res + (size_t)row * N + col);
                    vx += rv.x; vy += rv.y;
                }
                if (MODE == 2) { vx = fmaxf(vx, 0.f); vy = fmaxf(vy, 0.f); }
                if (MODE == 2 || MODE == 3) {
                    *reinterpret_cast<uint32_t*>(Oh + (size_t)row * N + col) =
                        h2u(__floats2half2_rn(vx, vy));
                } else {
                    *reinterpret_cast<float2*>(C + (size_t)row * N + col) =
                        make_float2(vx, vy);
                }
            }
        }
    }
}

// ---------------- fp16 tensor-core causal flash attention ------------------
// grid (SEQ/64, NH, BATCH), 128 threads (4 warps x 16 query rows), 4 CTA/SM.
#define ATTN_SMEM (2 * 16384)   // 2 stages x (K 8KB + V 8KB)

__global__ __launch_bounds__(128, 4) void attn_mma(
    const __half* __restrict__ qkv, __half* __restrict__ y)
{
    extern __shared__ char smem[];
    const uint32_t sb = smem_u32(smem);

    int qt = gridDim.x - 1 - blockIdx.x;   // heavy blocks first
    int h = blockIdx.y, b = blockIdx.z;
    int q0 = qt * 64;
    int tid = threadIdx.x, wid = tid >> 5, lane = tid & 31;
    const __half* base = qkv + (size_t)b * SEQ * 3 * DIM;
    const int r = lane >> 2, cb = (lane & 3) * 2;
    const __half2 QSC2 = __float2half2_rn(0.1803368801f);  // 0.125*log2(e)
    const uint32_t ONES[2] = {0x3C003C00u, 0x3C003C00u};   // half2(1,1) x2
    const __half NEGINF = __ushort_as_half(0xFC00u);

    uint32_t qf[4][4];
    #pragma unroll
    for (int ks = 0; ks < 4; ks++) {
        #pragma unroll
        for (int fr = 0; fr < 4; fr++) {
            int row = q0 + wid * 16 + r + (fr & 1) * 8;
            int col = ks * 16 + cb + (fr >> 1) * 8;
            __half2 v = *reinterpret_cast<const __half2*>(
                base + (size_t)row * 3 * DIM + h * HD + col);
            qf[ks][fr] = h2u(__hmul2(v, QSC2));
        }
    }

    auto issueKV = [&](int kb) {
        uint32_t stg = sb + (uint32_t)(kb & 1) * 16384;
        #pragma unroll
        for (int p = 0; p < 8; p++) {
            int idx = p * 128 + tid;
            int op = idx >> 9, rem = idx & 511;
            int row = rem >> 3, c = rem & 7;
            const __half* src = base + (size_t)(kb * 64 + row) * 3 * DIM
                              + (op ? 2 * DIM : DIM) + h * HD + c * 8;
            cp16(stg + op * 8192 + SWZ128((uint32_t)(row * 128 + c * 16)), src);
        }
        asm volatile("cp.async.commit_group;" ::: "memory");
    };

    float m0 = -1e30f, m1 = -1e30f;
    float lacc[4] = {0.f, 0.f, 0.f, 0.f};
    float o[8][4];
    #pragma unroll
    for (int ni = 0; ni < 8; ni++)
        #pragma unroll
        for (int c = 0; c < 4; c++) o[ni][c] = 0.f;

    const int last = qt;
    issueKV(0);
    for (int kb = 0; kb <= last; kb++) {
        asm volatile("cp.async.wait_group 0;" ::: "memory");
        __syncthreads();
        if (kb < last) issueKV(kb + 1);

        uint32_t sK = sb + (uint32_t)(kb & 1) * 16384;
        uint32_t sV = sK + 8192;

        uint32_t s16[8][2];
        #pragma unroll
        for (int ni = 0; ni < 8; ni++) { s16[ni][0] = 0; s16[ni][1] = 0; }
        #pragma unroll
        for (int ks = 0; ks < 4; ks++) {
            #pragma unroll
            for (int ni2 = 0; ni2 < 4; ni2++) {
                int krow = ni2 * 16 + ((lane & 16) >> 1) + (lane & 7);
                int kcolb = ks * 32 + (lane & 8) * 2;
                uint32_t kf[4];
                ldsm_x4(kf, sK + SWZ128((uint32_t)(krow * 128 + kcolb)));
                mma_f16h(s16[2 * ni2],     qf[ks], kf);
                mma_f16h(s16[2 * ni2 + 1], qf[ks], kf + 2);
            }
        }

        if (kb == last) {
            int rg0 = q0 + wid * 16 + r, rg1 = rg0 + 8;
            int cgb = kb * 64;
            #pragma unroll
            for (int ni = 0; ni < 8; ni++) {
                int c0 = cgb + ni * 8 + cb;
                __half2 v0 = u2h(s16[ni][0]);
                __half2 v1 = u2h(s16[ni][1]);
                if (c0     > rg0) v0.x = NEGINF;
                if (c0 + 1 > rg0) v0.y = NEGINF;
                if (c0     > rg1) v1.x = NEGINF;
                if (c0 + 1 > rg1) v1.y = NEGINF;
                s16[ni][0] = h2u(v0);
                s16[ni][1] = h2u(v1);
            }
        }

        __half2 mx0 = u2h(s16[0][0]), mx1 = u2h(s16[0][1]);
        #pragma unroll
        for (int ni = 1; ni < 8; ni++) {
            mx0 = __hmax2(mx0, u2h(s16[ni][0]));
            mx1 = __hmax2(mx1, u2h(s16[ni][1]));
        }
        uint32_t x0 = h2u(mx0), x1 = h2u(mx1);
        x0 = h2u(__hmax2(u2h(x0), u2h(__shfl_xor_sync(0xffffffffu, x0, 1))));
        x0 = h2u(__hmax2(u2h(x0), u2h(__shfl_xor_sync(0xffffffffu, x0, 2))));
        x1 = h2u(__hmax2(u2h(x1), u2h(__shfl_xor_sync(0xffffffffu, x1, 1))));
        x1 = h2u(__hmax2(u2h(x1), u2h(__shfl_xor_sync(0xffffffffu, x1, 2))));
        float nm0 = fmaxf(__half2float(u2h(x0).x), __half2float(u2h(x0).y));
        float nm1 = fmaxf(__half2float(u2h(x1).x), __half2float(u2h(x1).y));
        nm0 = fmaxf(nm0, m0);
        nm1 = fmaxf(nm1, m1);

        bool changed = !__all_sync(0xffffffffu, (nm0 == m0) & (nm1 == m1));
        if (changed) {
            float sc0 = ex2(m0 - nm0), sc1 = ex2(m1 - nm1);
            #pragma unroll
            for (int ni = 0; ni < 8; ni++) {
                o[ni][0] *= sc0; o[ni][1] *= sc0;
                o[ni][2] *= sc1; o[ni][3] *= sc1;
            }
            lacc[0] *= sc0; lacc[2] *= sc1;
        }
        m0 = nm0; m1 = nm1;

        __half2 nm0h = __float2half2_rn(nm0);
        __half2 nm1h = __float2half2_rn(nm1);
        uint32_t ph[4][4];
        #pragma unroll
        for (int t = 0; t < 4; t++) {
            ph[t][0] = h2u(h2exp2(__hsub2(u2h(s16[2 * t][0]),     nm0h)));
            ph[t][1] = h2u(h2exp2(__hsub2(u2h(s16[2 * t][1]),     nm1h)));
            ph[t][2] = h2u(h2exp2(__hsub2(u2h(s16[2 * t + 1][0]), nm0h)));
            ph[t][3] = h2u(h2exp2(__hsub2(u2h(s16[2 * t + 1][1]), nm1h)));
        }

        #pragma unroll
        for (int t = 0; t < 4; t++) {
            mma_f16(lacc, ph[t], ONES);
            #pragma unroll
            for (int ni2 = 0; ni2 < 4; ni2++) {
                int vrow = t * 16 + (lane & 15);
                int vcolb = ni2 * 32 + (lane & 16);
                uint32_t vf[4];
                ldsm_x4t(vf, sV + SWZ128((uint32_t)(vrow * 128 + vcolb)));
                mma_f16(o[2 * ni2],     ph[t], vf);
                mma_f16(o[2 * ni2 + 1], ph[t], vf + 2);
            }
        }
        __syncthreads();
    }

    float il0 = 1.0f / lacc[0], il1 = 1.0f / lacc[2];
    int row0 = b * SEQ + q0 + wid * 16 + r;
    #pragma unroll
    for (int ni = 0; ni < 8; ni++) {
        int col = h * HD + ni * 8 + cb;
        *reinterpret_cast<uint32_t*>(y + (size_t)row0 * DIM + col) =
            h2u(__floats2half2_rn(o[ni][0] * il0, o[ni][1] * il0));
        *reinterpret_cast<uint32_t*>(y + (size_t)(row0 + 8) * DIM + col) =
            h2u(__floats2half2_rn(o[ni][2] * il1, o[ni][3] * il1));
    }
}

// ---------------- launch ---------------------------------------------------
extern "C" void kernel_launch(void* const* d_in, const int* in_sizes, int n_in,
                              void* d_out, int out_size)
{
    const float* x      = (const float*)d_in[0];
    const float* ln1_g  = (const float*)d_in[1];
    const float* ln1_b  = (const float*)d_in[2];
    const float* ln2_g  = (const float*)d_in[3];
    const float* ln2_b  = (const float*)d_in[4];
    const float* W_qkv  = (const float*)d_in[5];
    const float* b_qkv  = (const float*)d_in[6];
    const float* W_proj = (const float*)d_in[7];
    const float* b_proj = (const float*)d_in[8];
    const float* W_fc   = (const float*)d_in[9];
    const float* b_fc   = (const float*)d_in[10];
    const float* W_out  = (const float*)d_in[11];
    const float* b_out  = (const float*)d_in[12];
    float* out = (float*)d_out;

    float *x1;
    __half *qkv, *h, *y, *act, *wq, *wp, *wf, *wo;
    cudaGetSymbolAddress((void**)&x1,  g_x1);
    cudaGetSymbolAddress((void**)&qkv, g_qkv);
    cudaGetSymbolAddress((void**)&h,   g_h);
    cudaGetSymbolAddress((void**)&y,   g_y);
    cudaGetSymbolAddress((void**)&act, g_act);
    cudaGetSymbolAddress((void**)&wq,  g_wq);
    cudaGetSymbolAddress((void**)&wp,  g_wp);
    cudaGetSymbolAddress((void**)&wf,  g_wf);
    cudaGetSymbolAddress((void**)&wo,  g_wo);

    cudaFuncSetAttribute(gemm_f16<1>,
        cudaFuncAttributeMaxDynamicSharedMemorySize, GEMM_SMEM);
    cudaFuncSetAttribute(gemm_f16<2>,
        cudaFuncAttributeMaxDynamicSharedMemorySize, GEMM_SMEM);
    cudaFuncSetAttribute(gemm_f16<3>,
        cudaFuncAttributeMaxDynamicSharedMemorySize, GEMM_SMEM);
    cudaFuncSetAttribute(attn_mma,
        cudaFuncAttributeMaxDynamicSharedMemorySize, ATTN_SMEM);

    // 0) weight transposes + LN1 fused in one launch
    prep_kernel<<<12288 + NTOK, 256>>>(W_qkv, W_proj, W_fc, W_out,
                                       wq, wp, wf, wo,
                                       x, ln1_g, ln1_b, h);

    // 1) qkv = h @ W_qkv + b_qkv (fp16 out)
    gemm_f16<3><<<dim3(3 * DIM / 64, NTOK / 128), 128, GEMM_SMEM>>>(
        h, wq, b_qkv, nullptr, nullptr, qkv, NTOK, 3 * DIM, DIM);

    // 2) attention -> y (fp16)
    attn_mma<<<dim3(SEQ / 64, NH, BATCH), 128, ATTN_SMEM>>>(qkv, y);

    // 3) x1 = x + y @ W_proj + b_proj
    gemm_f16<1><<<dim3(DIM / 64, NTOK / 128), 128, GEMM_SMEM>>>(
        y, wp, b_proj, x, x1, nullptr, NTOK, DIM, DIM);

    // 4) LN2 -> h (fp16)
    ln_kernel<<<NTOK, 256>>>(x1, ln2_g, ln2_b, h);

    // 5) act = relu(h @ W_fc + b_fc) (fp16)
    gemm_f16<2><<<dim3(4 * DIM / 64, NTOK / 128), 128, GEMM_SMEM>>>(
        h, wf, b_fc, nullptr, nullptr, act, NTOK, 4 * DIM, DIM);

    // 6) out = x1 + act @ W_out + b_out
    gemm_f16<1><<<dim3(DIM / 64, NTOK / 128), 128, GEMM_SMEM>>>(
        act, wo, b_out, x1, out, nullptr, NTOK, DIM, 4 * DIM);
}

// round 17
// speedup vs baseline: 1.0337x; 1.0337x over previous
#include <cuda_runtime.h>
#include <cuda_fp16.h>
#include <math.h>
#include <stdint.h>

#define BATCH 2
#define SEQ   2048
#define DIM   1024
#define NH    16
#define HD    64
#define NTOK  (BATCH * SEQ)   // 4096

// ---------------- scratch (device globals) ---------------------------------
__device__ float  g_x1 [(size_t)NTOK * DIM];       // residual after proj
__device__ __half g_qkv[(size_t)NTOK * 3 * DIM];   // qkv fp16
__device__ __half g_h  [(size_t)NTOK * DIM];       // LN out fp16
__device__ __half g_y  [(size_t)NTOK * DIM];       // attn out fp16
__device__ __half g_act[(size_t)NTOK * 4 * DIM];   // relu(fc) fp16
__device__ __half g_wq [(size_t)3 * DIM * DIM];    // W_qkv^T fp16
__device__ __half g_wp [(size_t)DIM * DIM];        // W_proj^T fp16
__device__ __half g_wf [(size_t)4 * DIM * DIM];    // W_fc^T fp16
__device__ __half g_wo [(size_t)4 * DIM * DIM];    // W_out^T fp16

// ======================= helpers ===========================================
__device__ __forceinline__ uint32_t smem_u32(const void* p) {
    uint32_t a;
    asm("{ .reg .u64 t; cvta.to.shared.u64 t, %1; cvt.u32.u64 %0, t; }"
        : "=r"(a) : "l"(p));
    return a;
}
#define SWZ128(o) ((o) ^ (((o) >> 3) & 0x70))

__device__ __forceinline__ void ldsm_x4(uint32_t* r, uint32_t addr) {
    asm volatile("ldmatrix.sync.aligned.m8n8.x4.shared.b16 {%0,%1,%2,%3}, [%4];"
                 : "=r"(r[0]), "=r"(r[1]), "=r"(r[2]), "=r"(r[3]) : "r"(addr));
}
__device__ __forceinline__ void ldsm_x4t(uint32_t* r, uint32_t addr) {
    asm volatile("ldmatrix.sync.aligned.m8n8.x4.trans.shared.b16 {%0,%1,%2,%3}, [%4];"
                 : "=r"(r[0]), "=r"(r[1]), "=r"(r[2]), "=r"(r[3]) : "r"(addr));
}
__device__ __forceinline__ void mma_f16(float* c, const uint32_t* a,
                                        const uint32_t* b) {
    asm volatile(
        "mma.sync.aligned.m16n8k16.row.col.f32.f16.f16.f32 "
        "{%0,%1,%2,%3}, {%4,%5,%6,%7}, {%8,%9}, {%0,%1,%2,%3};"
        : "+f"(c[0]), "+f"(c[1]), "+f"(c[2]), "+f"(c[3])
        : "r"(a[0]), "r"(a[1]), "r"(a[2]), "r"(a[3]), "r"(b[0]), "r"(b[1]));
}
// fp16-accumulator variant (2-reg D) for the QK logits
__device__ __forceinline__ void mma_f16h(uint32_t* c, const uint32_t* a,
                                         const uint32_t* b) {
    asm volatile(
        "mma.sync.aligned.m16n8k16.row.col.f16.f16.f16.f16 "
        "{%0,%1}, {%2,%3,%4,%5}, {%6,%7}, {%0,%1};"
        : "+r"(c[0]), "+r"(c[1])
        : "r"(a[0]), "r"(a[1]), "r"(a[2]), "r"(a[3]), "r"(b[0]), "r"(b[1]));
}
__device__ __forceinline__ void cp16(uint32_t daddr, const void* saddr) {
    asm volatile("cp.async.cg.shared.global [%0], [%1], 16;"
                 :: "r"(daddr), "l"(saddr));
}
__device__ __forceinline__ float ex2(float x) {
    float y;
    asm("ex2.approx.f32 %0, %1;" : "=f"(y) : "f"(x));
    return y;
}
__device__ __forceinline__ uint32_t h2u(__half2 v) {
    return *reinterpret_cast<uint32_t*>(&v);
}
__device__ __forceinline__ __half2 u2h(uint32_t v) {
    return *reinterpret_cast<__half2*>(&v);
}

// ---------------- LayerNorm body (fp16 out) --------------------------------
__device__ __forceinline__ void ln_body(
    const float* __restrict__ x, const float* __restrict__ gamma,
    const float* __restrict__ beta, __half* __restrict__ out, int row)
{
    int tid = threadIdx.x;
    const float4* xr = reinterpret_cast<const float4*>(x + (size_t)row * DIM);
    float4 v = xr[tid];
    float s1 = v.x + v.y + v.z + v.w;
    float s2 = v.x * v.x + v.y * v.y + v.z * v.z + v.w * v.w;
    #pragma unroll
    for (int o = 16; o > 0; o >>= 1) {
        s1 += __shfl_xor_sync(0xffffffffu, s1, o);
        s2 += __shfl_xor_sync(0xffffffffu, s2, o);
    }
    __shared__ float sh1[8], sh2[8];
    int w = tid >> 5, l = tid & 31;
    if (l == 0) { sh1[w] = s1; sh2[w] = s2; }
    __syncthreads();
    s1 = 0.f; s2 = 0.f;
    #pragma unroll
    for (int i = 0; i < 8; i++) { s1 += sh1[i]; s2 += sh2[i]; }
    float mu  = s1 * (1.0f / DIM);
    float var = s2 * (1.0f / DIM) - mu * mu;
    float r   = rsqrtf(var + 1e-5f);
    float4 gv = reinterpret_cast<const float4*>(gamma)[tid];
    float4 bv = reinterpret_cast<const float4*>(beta)[tid];
    uint2 u;
    u.x = h2u(__floats2half2_rn((v.x - mu) * r * gv.x + bv.x,
                                (v.y - mu) * r * gv.y + bv.y));
    u.y = h2u(__floats2half2_rn((v.z - mu) * r * gv.z + bv.z,
                                (v.w - mu) * r * gv.w + bv.w));
    *reinterpret_cast<uint2*>(out + (size_t)row * DIM + tid * 4) = u;
}

__global__ __launch_bounds__(256) void ln_kernel(
    const float* __restrict__ x, const float* __restrict__ gamma,
    const float* __restrict__ beta, __half* __restrict__ out)
{
    ln_body(x, gamma, beta, out, blockIdx.x);
}

// ---------------- prep: 4 weight transposes + LN1, one launch --------------
__global__ __launch_bounds__(256) void prep_kernel(
    const float* __restrict__ W0, const float* __restrict__ W1,
    const float* __restrict__ W2, const float* __restrict__ W3,
    __half* __restrict__ O0, __half* __restrict__ O1,
    __half* __restrict__ O2, __half* __restrict__ O3,
    const float* __restrict__ x, const float* __restrict__ ln1_g,
    const float* __restrict__ ln1_b, __half* __restrict__ h)
{
    int t = blockIdx.x;
    if (t >= 12288) {
        ln_body(x, ln1_g, ln1_b, h, t - 12288);
        return;
    }
    const float* in; __half* out; int R, C;
    if (t < 3072)      { in = W0; out = O0; R = DIM;     C = 3 * DIM; }
    else if (t < 4096) { in = W1; out = O1; R = DIM;     C = DIM;     t -= 3072; }
    else if (t < 8192) { in = W2; out = O2; R = DIM;     C = 4 * DIM; t -= 4096; }
    else               { in = W3; out = O3; R = 4 * DIM; C = DIM;     t -= 8192; }
    int tilesX = C >> 5;
    int bx = t % tilesX, by = t / tilesX;

    __shared__ float tt[32][33];
    int tx = threadIdx.x & 31, ty = threadIdx.x >> 5;
    int x0 = bx * 32 + tx;
    #pragma unroll
    for (int j = 0; j < 32; j += 8)
        tt[ty + j][tx] = in[(size_t)(by * 32 + ty + j) * C + x0];
    __syncthreads();
    #pragma unroll
    for (int j = 0; j < 32; j += 8) {
        size_t idx = (size_t)(bx * 32 + ty + j) * R + by * 32 + tx;
        out[idx] = __float2half(tt[tx][ty + j]);
    }
}

// ---------------- fp16 GEMM (128x64 tile, 3-stage, 128 thr, 3 CTA/SM) ------
// A [M,K] fp16 row-major; B [N,K] fp16 row-major. fp32 accumulate.
// 4 warps (2m x 2n), warp tile 64x32. Stage = A 16KB + B 8KB = 24KB.
// Round-15 proven pipeline: wait_group 1, single barrier, issue(i+2).
#define STAGE_BYTES 24576
#define GEMM_STAGES 3
#define GEMM_SMEM   (GEMM_STAGES * STAGE_BYTES)

template<int MODE>   // 0: fp32+bias; 1: fp32+bias+res; 2: fp16 relu; 3: fp16
__global__ __launch_bounds__(128, 3) void gemm_f16(
    const __half* __restrict__ A, const __half* __restrict__ B,
    const float* __restrict__ bias, const float* __restrict__ res,
    float* __restrict__ C, __half* __restrict__ Oh, int M, int N, int K)
{
    extern __shared__ char smem[];
    const uint32_t sbase = smem_u32(smem);
    const int tid = threadIdx.x;
    const int wid = tid >> 5, lane = tid & 31;
    const int m0 = blockIdx.y * 128, n0 = blockIdx.x * 64;
    const int wm = (wid & 1) * 64;
    const int wn = (wid >> 1) * 32;

    float acc[4][4][4];
    #pragma unroll
    for (int a = 0; a < 4; a++)
        #pragma unroll
        for (int b = 0; b < 4; b++)
            #pragma unroll
            for (int c = 0; c < 4; c++) acc[a][b][c] = 0.f;

    const __half* Ab = A + (size_t)m0 * K;
    const __half* Bb = B + (size_t)n0 * K;

    // stage layout: A tile 16KB (128 rows x 128B), B tile 8KB (64 rows x 128B)
    auto issue = [&](int i) {
        int k0 = i << 6;
        uint32_t st = sbase + (uint32_t)(i % GEMM_STAGES) * STAGE_BYTES;
        #pragma unroll
        for (int p = 0; p < 12; p++) {
            int idx = p * 128 + tid;              // 0..1535 (16B chunks)
            if (idx < 1024) {
                int row = idx >> 3, c = idx & 7;
                cp16(st + SWZ128((uint32_t)(row * 128 + c * 16)),
                     Ab + (size_t)row * K + k0 + c * 8);
            } else {
                int rem = idx - 1024;
                int row = rem >> 3, c = rem & 7;
                cp16(st + 16384 + SWZ128((uint32_t)(row * 128 + c * 16)),
                     Bb + (size_t)row * K + k0 + c * 8);
            }
        }
        asm volatile("cp.async.commit_group;" ::: "memory");
    };

    const int NC = K >> 6;
    issue(0); issue(1);
    for (int i = 0; i < NC; i++) {
        if (i + 1 < NC) { asm volatile("cp.async.wait_group 1;" ::: "memory"); }
        else            { asm volatile("cp.async.wait_group 0;" ::: "memory"); }
        __syncthreads();   // fill(i) visible; all warps done with slot (i-1)%3
        if (i + 2 < NC) issue(i + 2);   // targets slot (i-1)%3: safe

        uint32_t st = sbase + (uint32_t)(i % GEMM_STAGES) * STAGE_BYTES;
        uint32_t sA = st, sB = st + 16384;

        #pragma unroll
        for (int ks = 0; ks < 4; ks++) {
            uint32_t af[4][4];
            #pragma unroll
            for (int mi = 0; mi < 4; mi++) {
                int row = wm + mi * 16 + (lane & 15);
                int colb = ks * 32 + (lane >> 4) * 16;
                ldsm_x4(af[mi], sA + SWZ128((uint32_t)(row * 128 + colb)));
            }
            uint32_t bf[2][4];
            #pragma unroll
            for (int ni2 = 0; ni2 < 2; ni2++) {
                int row = wn + ni2 * 16 + ((lane & 16) >> 1) + (lane & 7);
                int colb = ks * 32 + (lane & 8) * 2;
                ldsm_x4(bf[ni2], sB + SWZ128((uint32_t)(row * 128 + colb)));
            }
            #pragma unroll
            for (int mi = 0; mi < 4; mi++)
                #pragma unroll
                for (int ni2 = 0; ni2 < 2; ni2++) {
                    mma_f16(acc[mi][2 * ni2],     af[mi], bf[ni2]);
                    mma_f16(acc[mi][2 * ni2 + 1], af[mi], bf[ni2] + 2);
                }
        }
    }

    #pragma unroll
    for (int mi = 0; mi < 4; mi++) {
        #pragma unroll
        for (int h = 0; h < 2; h++) {
            int row = m0 + wm + mi * 16 + (lane >> 2) + h * 8;
            #pragma unroll
            for (int ni = 0; ni < 4; ni++) {
                int col = n0 + wn + ni * 8 + (lane & 3) * 2;
                float2 bb = *reinterpret_cast<const float2*>(bias + col);
                float vx = acc[mi][ni][h * 2 + 0] + bb.x;
                float vy = acc[mi][ni][h * 2 + 1] + bb.y;
                if (MODE == 1) {
                    float2 rv = *reinterpret_cast<const float2*>(
                        res + (size_t)row * N + col);
                    vx += rv.x; vy += rv.y;
                }
                if (MODE == 2) { vx = fmaxf(vx, 0.f); vy = fmaxf(vy, 0.f); }
                if (MODE == 2 || MODE == 3) {
                    *reinterpret_cast<uint32_t*>(Oh + (size_t)row * N + col) =
                        h2u(__floats2half2_rn(vx, vy));
                } else {
                    *reinterpret_cast<float2*>(C + (size_t)row * N + col) =
                        make_float2(vx, vy);
                }
            }
        }
    }
}

// ---------------- fp16 tensor-core causal flash attention ------------------
// grid (SEQ/64, NH, BATCH), 128 threads (4 warps x 16 query rows), 4 CTA/SM.
#define ATTN_SMEM (2 * 16384)   // 2 stages x (K 8KB + V 8KB)

__global__ __launch_bounds__(128, 4) void attn_mma(
    const __half* __restrict__ qkv, __half* __restrict__ y)
{
    extern __shared__ char smem[];
    const uint32_t sb = smem_u32(smem);

    int qt = gridDim.x - 1 - blockIdx.x;   // heavy blocks first
    int h = blockIdx.y, b = blockIdx.z;
    int q0 = qt * 64;
    int tid = threadIdx.x, wid = tid >> 5, lane = tid & 31;
    const __half* base = qkv + (size_t)b * SEQ * 3 * DIM;
    const int r = lane >> 2, cb = (lane & 3) * 2;
    const __half2 QSC2 = __float2half2_rn(0.1803368801f);  // 0.125*log2(e)
    const uint32_t ONES[2] = {0x3C003C00u, 0x3C003C00u};   // half2(1,1) x2
    const __half NEGINF = __ushort_as_half(0xFC00u);

    uint32_t qf[4][4];
    #pragma unroll
    for (int ks = 0; ks < 4; ks++) {
        #pragma unroll
        for (int fr = 0; fr < 4; fr++) {
            int row = q0 + wid * 16 + r + (fr & 1) * 8;
            int col = ks * 16 + cb + (fr >> 1) * 8;
            __half2 v = *reinterpret_cast<const __half2*>(
                base + (size_t)row * 3 * DIM + h * HD + col);
            qf[ks][fr] = h2u(__hmul2(v, QSC2));
        }
    }

    auto issueKV = [&](int kb) {
        uint32_t stg = sb + (uint32_t)(kb & 1) * 16384;
        #pragma unroll
        for (int p = 0; p < 8; p++) {
            int idx = p * 128 + tid;
            int op = idx >> 9, rem = idx & 511;
            int row = rem >> 3, c = rem & 7;
            const __half* src = base + (size_t)(kb * 64 + row) * 3 * DIM
                              + (op ? 2 * DIM : DIM) + h * HD + c * 8;
            cp16(stg + op * 8192 + SWZ128((uint32_t)(row * 128 + c * 16)), src);
        }
        asm volatile("cp.async.commit_group;" ::: "memory");
    };

    float m0 = -1e30f, m1 = -1e30f;
    float lacc[4] = {0.f, 0.f, 0.f, 0.f};
    float o[8][4];
    #pragma unroll
    for (int ni = 0; ni < 8; ni++)
        #pragma unroll
        for (int c = 0; c < 4; c++) o[ni][c] = 0.f;

    const int last = qt;
    issueKV(0);
    for (int kb = 0; kb <= last; kb++) {
        asm volatile("cp.async.wait_group 0;" ::: "memory");
        __syncthreads();
        if (kb < last) issueKV(kb + 1);

        uint32_t sK = sb + (uint32_t)(kb & 1) * 16384;
        uint32_t sV = sK + 8192;

        uint32_t s16[8][2];
        #pragma unroll
        for (int ni = 0; ni < 8; ni++) { s16[ni][0] = 0; s16[ni][1] = 0; }
        #pragma unroll
        for (int ks = 0; ks < 4; ks++) {
            #pragma unroll
            for (int ni2 = 0; ni2 < 4; ni2++) {
                int krow = ni2 * 16 + ((lane & 16) >> 1) + (lane & 7);
                int kcolb = ks * 32 + (lane & 8) * 2;
                uint32_t kf[4];
                ldsm_x4(kf, sK + SWZ128((uint32_t)(krow * 128 + kcolb)));
                mma_f16h(s16[2 * ni2],     qf[ks], kf);
                mma_f16h(s16[2 * ni2 + 1], qf[ks], kf + 2);
            }
        }

        if (kb == last) {
            int rg0 = q0 + wid * 16 + r, rg1 = rg0 + 8;
            int cgb = kb * 64;
            #pragma unroll
            for (int ni = 0; ni < 8; ni++) {
                int c0 = cgb + ni * 8 + cb;
                __half2 v0 = u2h(s16[ni][0]);
                __half2 v1 = u2h(s16[ni][1]);
                if (c0     > rg0) v0.x = NEGINF;
                if (c0 + 1 > rg0) v0.y = NEGINF;
                if (c0     > rg1) v1.x = NEGINF;
                if (c0 + 1 > rg1) v1.y = NEGINF;
                s16[ni][0] = h2u(v0);
                s16[ni][1] = h2u(v1);
            }
        }

        __half2 mx0 = u2h(s16[0][0]), mx1 = u2h(s16[0][1]);
        #pragma unroll
        for (int ni = 1; ni < 8; ni++) {
            mx0 = __hmax2(mx0, u2h(s16[ni][0]));
            mx1 = __hmax2(mx1, u2h(s16[ni][1]));
        }
        uint32_t x0 = h2u(mx0), x1 = h2u(mx1);
        x0 = h2u(__hmax2(u2h(x0), u2h(__shfl_xor_sync(0xffffffffu, x0, 1))));
        x0 = h2u(__hmax2(u2h(x0), u2h(__shfl_xor_sync(0xffffffffu, x0, 2))));
        x1 = h2u(__hmax2(u2h(x1), u2h(__shfl_xor_sync(0xffffffffu, x1, 1))));
        x1 = h2u(__hmax2(u2h(x1), u2h(__shfl_xor_sync(0xffffffffu, x1, 2))));
        float nm0 = fmaxf(__half2float(u2h(x0).x), __half2float(u2h(x0).y));
        float nm1 = fmaxf(__half2float(u2h(x1).x), __half2float(u2h(x1).y));
        nm0 = fmaxf(nm0, m0);
        nm1 = fmaxf(nm1, m1);

        bool changed = !__all_sync(0xffffffffu, (nm0 == m0) & (nm1 == m1));
        if (changed) {
            float sc0 = ex2(m0 - nm0), sc1 = ex2(m1 - nm1);
            #pragma unroll
            for (int ni = 0; ni < 8; ni++) {
                o[ni][0] *= sc0; o[ni][1] *= sc0;
                o[ni][2] *= sc1; o[ni][3] *= sc1;
            }
            lacc[0] *= sc0; lacc[2] *= sc1;
        }
        m0 = nm0; m1 = nm1;

        __half2 nm0h = __float2half2_rn(nm0);
        __half2 nm1h = __float2half2_rn(nm1);
        uint32_t ph[4][4];
        #pragma unroll
        for (int t = 0; t < 4; t++) {
            ph[t][0] = h2u(h2exp2(__hsub2(u2h(s16[2 * t][0]),     nm0h)));
            ph[t][1] = h2u(h2exp2(__hsub2(u2h(s16[2 * t][1]),     nm1h)));
            ph[t][2] = h2u(h2exp2(__hsub2(u2h(s16[2 * t + 1][0]), nm0h)));
            ph[t][3] = h2u(h2exp2(__hsub2(u2h(s16[2 * t + 1][1]), nm1h)));
        }

        #pragma unroll
        for (int t = 0; t < 4; t++) {
            mma_f16(lacc, ph[t], ONES);
            #pragma unroll
            for (int ni2 = 0; ni2 < 4; ni2++) {
                int vrow = t * 16 + (lane & 15);
                int vcolb = ni2 * 32 + (lane & 16);
                uint32_t vf[4];
                ldsm_x4t(vf, sV + SWZ128((uint32_t)(vrow * 128 + vcolb)));
                mma_f16(o[2 * ni2],     ph[t], vf);
                mma_f16(o[2 * ni2 + 1], ph[t], vf + 2);
            }
        }
        __syncthreads();
    }

    float il0 = 1.0f / lacc[0], il1 = 1.0f / lacc[2];
    int row0 = b * SEQ + q0 + wid * 16 + r;
    #pragma unroll
    for (int ni = 0; ni < 8; ni++) {
        int col = h * HD + ni * 8 + cb;
        *reinterpret_cast<uint32_t*>(y + (size_t)row0 * DIM + col) =
            h2u(__floats2half2_rn(o[ni][0] * il0, o[ni][1] * il0));
        *reinterpret_cast<uint32_t*>(y + (size_t)(row0 + 8) * DIM + col) =
            h2u(__floats2half2_rn(o[ni][2] * il1, o[ni][3] * il1));
    }
}

// ---------------- launch ---------------------------------------------------
extern "C" void kernel_launch(void* const* d_in, const int* in_sizes, int n_in,
                              void* d_out, int out_size)
{
    const float* x      = (const float*)d_in[0];
    const float* ln1_g  = (const float*)d_in[1];
    const float* ln1_b  = (const float*)d_in[2];
    const float* ln2_g  = (const float*)d_in[3];
    const float* ln2_b  = (const float*)d_in[4];
    const float* W_qkv  = (const float*)d_in[5];
    const float* b_qkv  = (const float*)d_in[6];
    const float* W_proj = (const float*)d_in[7];
    const float* b_proj = (const float*)d_in[8];
    const float* W_fc   = (const float*)d_in[9];
    const float* b_fc   = (const float*)d_in[10];
    const float* W_out  = (const float*)d_in[11];
    const float* b_out  = (const float*)d_in[12];
    float* out = (float*)d_out;

    float *x1;
    __half *qkv, *h, *y, *act, *wq, *wp, *wf, *wo;
    cudaGetSymbolAddress((void**)&x1,  g_x1);
    cudaGetSymbolAddress((void**)&qkv, g_qkv);
    cudaGetSymbolAddress((void**)&h,   g_h);
    cudaGetSymbolAddress((void**)&y,   g_y);
    cudaGetSymbolAddress((void**)&act, g_act);
    cudaGetSymbolAddress((void**)&wq,  g_wq);
    cudaGetSymbolAddress((void**)&wp,  g_wp);
    cudaGetSymbolAddress((void**)&wf,  g_wf);
    cudaGetSymbolAddress((void**)&wo,  g_wo);

    cudaFuncSetAttribute(gemm_f16<1>,
        cudaFuncAttributeMaxDynamicSharedMemorySize, GEMM_SMEM);
    cudaFuncSetAttribute(gemm_f16<2>,
        cudaFuncAttributeMaxDynamicSharedMemorySize, GEMM_SMEM);
    cudaFuncSetAttribute(gemm_f16<3>,
        cudaFuncAttributeMaxDynamicSharedMemorySize, GEMM_SMEM);
    cudaFuncSetAttribute(attn_mma,
        cudaFuncAttributeMaxDynamicSharedMemorySize, ATTN_SMEM);

    // 0) weight transposes + LN1 fused in one launch
    prep_kernel<<<12288 + NTOK, 256>>>(W_qkv, W_proj, W_fc, W_out,
                                       wq, wp, wf, wo,
                                       x, ln1_g, ln1_b, h);

    // 1) qkv = h @ W_qkv + b_qkv (fp16 out)
    gemm_f16<3><<<dim3(3 * DIM / 64, NTOK / 128), 128, GEMM_SMEM>>>(
        h, wq, b_qkv, nullptr, nullptr, qkv, NTOK, 3 * DIM, DIM);

    // 2) attention -> y (fp16)
    attn_mma<<<dim3(SEQ / 64, NH, BATCH), 128, ATTN_SMEM>>>(qkv, y);

    // 3) x1 = x + y @ W_proj + b_proj
    gemm_f16<1><<<dim3(DIM / 64, NTOK / 128), 128, GEMM_SMEM>>>(
        y, wp, b_proj, x, x1, nullptr, NTOK, DIM, DIM);

    // 4) LN2 -> h (fp16)
    ln_kernel<<<NTOK, 256>>>(x1, ln2_g, ln2_b, h);

    // 5) act = relu(h @ W_fc + b_fc) (fp16)
    gemm_f16<2><<<dim3(4 * DIM / 64, NTOK / 128), 128, GEMM_SMEM>>>(
        h, wf, b_fc, nullptr, nullptr, act, NTOK, 4 * DIM, DIM);

    // 6) out = x1 + act @ W_out + b_out
    gemm_f16<1><<<dim3(DIM / 64, NTOK / 128), 128, GEMM_SMEM>>>(
        act, wo, b_out, x1, out, nullptr, NTOK, DIM, 4 * DIM);
}